// round 10
// baseline (speedup 1.0000x reference)
#include <cuda_runtime.h>
#include <cuda_fp16.h>

#define DDIM    256
#define NMAX    8192
#define LISTCAP 768     // mean nnz ~164, sd ~12.7; cnt+8 pad always fits
#define BW      4       // batch (software-pipelined)

// Scratch: NORMALIZED y rows in fp16 (4 MB, L2-resident) + norms (fp32)
// + CSR-style neighbor lists built by csr_scan.
__device__ __half2        g_yn16[(size_t)NMAX * (DDIM / 2)];
__device__ float          g_ynorm[NMAX];
__device__ unsigned short g_list[(size_t)NMAX * LISTCAP];
__device__ int            g_cnt[NMAX];

__device__ __forceinline__ float warp_sum(float v) {
#pragma unroll
    for (int off = 16; off; off >>= 1)
        v += __shfl_xor_sync(0xffffffffu, v, off);
    return v;
}

__device__ __forceinline__ __half2 h2shfl_xor(__half2 h, int off) {
    unsigned u = *(unsigned*)&h;
    u = __shfl_xor_sync(0xffffffffu, u, off);
    return *(__half2*)&u;
}

// Streaming pass: one CTA per adj row. 8 warps scan disjoint 1024-col
// segments (8 float4 loads in flight), ballot-compact nonzero indices.
// Warp 0 additionally preps y row `row` (fp16 normalized copy + norm).
// Tail zero-padded for the consumer's ushort4 reads.
__global__ void __launch_bounds__(256) csr_scan(const float* __restrict__ adj,
                                                const float* __restrict__ y,
                                                int M) {
    __shared__ int s_cnt;
    const int row  = blockIdx.x;
    const int tid  = threadIdx.x;
    const int wib  = tid >> 5;
    const int lane = tid & 31;

    if (tid == 0) s_cnt = 0;
    __syncthreads();

    // ---- warp 0: prep y row (independent of scan) ----
    if (wib == 0 && row < M) {
        const float4* yp = (const float4*)(y + (size_t)row * DDIM);
        float4 a = yp[lane * 2];
        float4 b = yp[lane * 2 + 1];
        float ss = a.x * a.x + a.y * a.y + a.z * a.z + a.w * a.w
                 + b.x * b.x + b.y * b.y + b.z * b.z + b.w * b.w;
        ss = warp_sum(ss);
        float n   = fmaxf(sqrtf(ss), 1e-8f);
        float inv = 1.0f / n;
        if (lane == 0) g_ynorm[row] = n;
        __half2* o = g_yn16 + (size_t)row * (DDIM / 2) + lane * 4;
        o[0] = __floats2half2_rn(a.x * inv, a.y * inv);
        o[1] = __floats2half2_rn(a.z * inv, a.w * inv);
        o[2] = __floats2half2_rn(b.x * inv, b.y * inv);
        o[3] = __floats2half2_rn(b.z * inv, b.w * inv);
    }

    const float* arow = adj + (size_t)row * M;
    unsigned short* lst = g_list + (size_t)row * LISTCAP;
    const unsigned lt = (1u << lane) - 1u;

    for (int seg = wib * 1024; seg < M; seg += 8 * 1024) {
        float4 a[8];
#pragma unroll
        for (int u = 0; u < 8; ++u)
            a[u] = __ldcs((const float4*)(arow + seg + u * 128 + lane * 4));

#pragma unroll
        for (int u = 0; u < 8; ++u) {
            int jb = seg + u * 128 + lane * 4;
            unsigned m0 = __ballot_sync(0xffffffffu, a[u].x != 0.f);
            unsigned m1 = __ballot_sync(0xffffffffu, a[u].y != 0.f);
            unsigned m2 = __ballot_sync(0xffffffffu, a[u].z != 0.f);
            unsigned m3 = __ballot_sync(0xffffffffu, a[u].w != 0.f);
            int c0 = __popc(m0), c1 = __popc(m1), c2 = __popc(m2), c3 = __popc(m3);
            int tot = c0 + c1 + c2 + c3;
            int base = 0;
            if (tot) {
                if (lane == 0) base = atomicAdd(&s_cnt, tot);
                base = __shfl_sync(0xffffffffu, base, 0);
                if (a[u].x != 0.f) lst[base + __popc(m0 & lt)]                = (unsigned short)(jb);
                if (a[u].y != 0.f) lst[base + c0 + __popc(m1 & lt)]           = (unsigned short)(jb + 1);
                if (a[u].z != 0.f) lst[base + c0 + c1 + __popc(m2 & lt)]      = (unsigned short)(jb + 2);
                if (a[u].w != 0.f) lst[base + c0 + c1 + c2 + __popc(m3 & lt)] = (unsigned short)(jb + 3);
            }
        }
    }
    __syncthreads();
    if (tid == 0) g_cnt[row] = s_cnt;
    if (tid < 8) lst[s_cnt + tid] = 0;   // pad for ushort4 reads
}

// One WARP per output row, software-pipelined over ~41 batches of 4:
// 2-deep index prefetch, 1-deep gather prefetch, half2 dot + packed 6-SHFL
// half2 reduction, fp16 P@y accumulation flushed to fp32 every 8 batches.
// No CTA barriers, no smem.
__global__ void __launch_bounds__(256) gat_main(const float* __restrict__ x,
                                                float* __restrict__ out,
                                                int N, int M) {
    const int warp = (blockIdx.x * blockDim.x + threadIdx.x) >> 5;
    const int lane = threadIdx.x & 31;
    if (warp >= N) return;
    const int i = warp;

    // ---- Load + normalize x row (lane owns dims [8l, 8l+8)) ----
    const float4* xp = (const float4*)(x + (size_t)i * DDIM);
    float4 xa = xp[lane * 2];
    float4 xb = xp[lane * 2 + 1];
    float ss = xa.x * xa.x + xa.y * xa.y + xa.z * xa.z + xa.w * xa.w
             + xb.x * xb.x + xb.y * xb.y + xb.z * xb.z + xb.w * xb.w;
    ss = warp_sum(ss);
    float xinv = 1.0f / fmaxf(sqrtf(ss), 1e-8f);

    __half2 xh0 = __floats2half2_rn(xa.x * xinv, xa.y * xinv);
    __half2 xh1 = __floats2half2_rn(xa.z * xinv, xa.w * xinv);
    __half2 xh2 = __floats2half2_rn(xb.x * xinv, xb.y * xinv);
    __half2 xh3 = __floats2half2_rn(xb.z * xinv, xb.w * xinv);

    const int cnt = g_cnt[i];
    const unsigned short* glst = g_list + (size_t)i * LISTCAP;
    const int nb = (cnt + BW - 1) / BW;

    // fp32 output accumulators + half2 partials (flushed every 8 batches)
    float o0 = 0.f, o1 = 0.f, o2 = 0.f, o3 = 0.f;
    float o4 = 0.f, o5 = 0.f, o6 = 0.f, o7 = 0.f;
    __half2 oh0 = __float2half2_rn(0.f);
    __half2 oh1 = oh0, oh2 = oh0, oh3 = oh0;
    float l = 0.f;

    const bool lo16 = (lane & 16) == 0;
    const bool lo8  = (lane & 8)  == 0;

    // ---- Pipeline prologue ----
    ushort4 pj[2];
    uint4   v[2][BW];
    float   yn[2][BW];

    pj[0] = *(const ushort4*)(glst);                       // batch 0 indices
    if (nb > 1) pj[1] = *(const ushort4*)(glst + 4);       // batch 1 indices
    {
        int j0[4] = { pj[0].x, pj[0].y, pj[0].z, pj[0].w };
#pragma unroll
        for (int k = 0; k < BW; ++k) {
            v[0][k]  = *(const uint4*)(g_yn16 + (size_t)j0[k] * (DDIM / 2) + lane * 4);
            yn[0][k] = __ldg(&g_ynorm[j0[k]]);
        }
    }

    for (int b = 0; b < nb; ++b) {
        const int cur = b & 1, nxt = cur ^ 1;

        // Prefetch gathers for batch b+1 (indices already in pj[nxt]).
        if (b + 1 < nb) {
            int jn[4] = { pj[nxt].x, pj[nxt].y, pj[nxt].z, pj[nxt].w };
#pragma unroll
            for (int k = 0; k < BW; ++k) {
                v[nxt][k]  = *(const uint4*)(g_yn16 + (size_t)jn[k] * (DDIM / 2) + lane * 4);
                yn[nxt][k] = __ldg(&g_ynorm[jn[k]]);
            }
        }
        // Prefetch indices for batch b+2 (pj[cur] no longer needed).
        if (b + 2 < nb)
            pj[cur] = *(const ushort4*)(glst + (b + 2) * 4);

        // ---- Process batch b ----
        __half2 dh[BW];
#pragma unroll
        for (int k = 0; k < BW; ++k) {
            __half2 acc = __hmul2(xh0, *(const __half2*)&v[cur][k].x);
            acc = __hfma2(xh1, *(const __half2*)&v[cur][k].y, acc);
            acc = __hfma2(xh2, *(const __half2*)&v[cur][k].z, acc);
            acc = __hfma2(xh3, *(const __half2*)&v[cur][k].w, acc);
            dh[k] = acc;
        }

        // Packed 4-value reduction in half2: 6 SHFL + 6 HADD2.
        {
            __half2 s0 = lo16 ? dh[2] : dh[0];
            dh[0] = __hadd2(lo16 ? dh[0] : dh[2], h2shfl_xor(s0, 16));
            __half2 s1 = lo16 ? dh[3] : dh[1];
            dh[1] = __hadd2(lo16 ? dh[1] : dh[3], h2shfl_xor(s1, 16));
            __half2 s2 = lo8 ? dh[1] : dh[0];
            dh[0] = __hadd2(lo8 ? dh[0] : dh[1], h2shfl_xor(s2, 8));
            dh[0] = __hadd2(dh[0], h2shfl_xor(dh[0], 4));
            dh[0] = __hadd2(dh[0], h2shfl_xor(dh[0], 2));
            dh[0] = __hadd2(dh[0], h2shfl_xor(dh[0], 1));
        }

        float2 cf = __half22float2(dh[0]);
        float e = __expf(cf.x + cf.y - 1.0f);   // fixed-shift softmax (cos <= 1)

        const int base = b * BW;
#pragma unroll
        for (int k = 0; k < BW; ++k) {
            float ek = __shfl_sync(0xffffffffu, e, 8 * k);
            float p  = (base + k < cnt) ? ek : 0.f;
            l += p;
            __half2 ph = __float2half2_rn(p * yn[cur][k]);   // p * ||y||
            oh0 = __hfma2(ph, *(const __half2*)&v[cur][k].x, oh0);
            oh1 = __hfma2(ph, *(const __half2*)&v[cur][k].y, oh1);
            oh2 = __hfma2(ph, *(const __half2*)&v[cur][k].z, oh2);
            oh3 = __hfma2(ph, *(const __half2*)&v[cur][k].w, oh3);
        }

        // Flush half2 partials to fp32 every 8 batches (32 neighbors).
        if ((b & 7) == 7) {
            float2 f0 = __half22float2(oh0), f1 = __half22float2(oh1);
            float2 f2 = __half22float2(oh2), f3 = __half22float2(oh3);
            o0 += f0.x; o1 += f0.y; o2 += f1.x; o3 += f1.y;
            o4 += f2.x; o5 += f2.y; o6 += f3.x; o7 += f3.y;
            __half2 z = __float2half2_rn(0.f);
            oh0 = z; oh1 = z; oh2 = z; oh3 = z;
        }
    }

    // Final flush
    {
        float2 f0 = __half22float2(oh0), f1 = __half22float2(oh1);
        float2 f2 = __half22float2(oh2), f3 = __half22float2(oh3);
        o0 += f0.x; o1 += f0.y; o2 += f1.x; o3 += f1.y;
        o4 += f2.x; o5 += f2.y; o6 += f3.x; o7 += f3.y;
    }

    float s = 0.5f / l;   // l > 0 guaranteed (diagonal entry in adj)
    float4 r0, r1;
    r0.x = fmaf(s, o0, 0.5f * xa.x);
    r0.y = fmaf(s, o1, 0.5f * xa.y);
    r0.z = fmaf(s, o2, 0.5f * xa.z);
    r0.w = fmaf(s, o3, 0.5f * xa.w);
    r1.x = fmaf(s, o4, 0.5f * xb.x);
    r1.y = fmaf(s, o5, 0.5f * xb.y);
    r1.z = fmaf(s, o6, 0.5f * xb.z);
    r1.w = fmaf(s, o7, 0.5f * xb.w);

    float4* op = (float4*)(out + (size_t)i * DDIM);
    op[lane * 2]     = r0;
    op[lane * 2 + 1] = r1;
}

extern "C" void kernel_launch(void* const* d_in, const int* in_sizes, int n_in,
                              void* d_out, int out_size) {
    const float* x   = (const float*)d_in[0];
    const float* y   = (const float*)d_in[1];
    const float* adj = (const float*)d_in[2];
    float* out       = (float*)d_out;

    int N = in_sizes[0] / DDIM;   // 8192
    int M = in_sizes[1] / DDIM;   // 8192

    csr_scan<<<N, 256>>>(adj, y, M);

    int main_blocks = (N * 32 + 255) / 256;
    gat_main<<<main_blocks, 256>>>(x, out, N, M);
}

// round 11
// speedup vs baseline: 2.0009x; 2.0009x over previous
#include <cuda_runtime.h>
#include <cuda_fp16.h>

#define DDIM    256
#define NMAX    8192
#define LISTCAP 768     // mean nnz ~164, sd ~12.7; cnt+8 pad always fits
#define BW      4       // batch (software-pipelined)

// Scratch: NORMALIZED y rows in fp16 (4 MB, L2-resident) + norms (fp32)
// + CSR-style neighbor lists built by csr_scan.
__device__ __half2        g_yn16[(size_t)NMAX * (DDIM / 2)];
__device__ float          g_ynorm[NMAX];
__device__ unsigned short g_list[(size_t)NMAX * LISTCAP];
__device__ int            g_cnt[NMAX];

__device__ __forceinline__ float warp_sum(float v) {
#pragma unroll
    for (int off = 16; off; off >>= 1)
        v += __shfl_xor_sync(0xffffffffu, v, off);
    return v;
}

__device__ __forceinline__ __half2 h2shfl_xor(__half2 h, int off) {
    unsigned u = *(unsigned*)&h;
    u = __shfl_xor_sync(0xffffffffu, u, off);
    return *(__half2*)&u;
}

// Streaming pass: one CTA per adj row. 8 warps scan disjoint 1024-col
// segments (8 float4 loads in flight), ballot-compact nonzero indices.
// Warp 0 additionally preps y row `row`. Tail zero-padded for ushort4 reads.
__global__ void __launch_bounds__(256) csr_scan(const float* __restrict__ adj,
                                                const float* __restrict__ y,
                                                int M) {
    __shared__ int s_cnt;
    const int row  = blockIdx.x;
    const int tid  = threadIdx.x;
    const int wib  = tid >> 5;
    const int lane = tid & 31;

    if (tid == 0) s_cnt = 0;
    __syncthreads();

    // ---- warp 0: prep y row (independent of scan) ----
    if (wib == 0 && row < M) {
        const float4* yp = (const float4*)(y + (size_t)row * DDIM);
        float4 a = yp[lane * 2];
        float4 b = yp[lane * 2 + 1];
        float ss = a.x * a.x + a.y * a.y + a.z * a.z + a.w * a.w
                 + b.x * b.x + b.y * b.y + b.z * b.z + b.w * b.w;
        ss = warp_sum(ss);
        float n   = fmaxf(sqrtf(ss), 1e-8f);
        float inv = 1.0f / n;
        if (lane == 0) g_ynorm[row] = n;
        __half2* o = g_yn16 + (size_t)row * (DDIM / 2) + lane * 4;
        o[0] = __floats2half2_rn(a.x * inv, a.y * inv);
        o[1] = __floats2half2_rn(a.z * inv, a.w * inv);
        o[2] = __floats2half2_rn(b.x * inv, b.y * inv);
        o[3] = __floats2half2_rn(b.z * inv, b.w * inv);
    }

    const float* arow = adj + (size_t)row * M;
    unsigned short* lst = g_list + (size_t)row * LISTCAP;
    const unsigned lt = (1u << lane) - 1u;

    for (int seg = wib * 1024; seg < M; seg += 8 * 1024) {
        float4 a[8];
#pragma unroll
        for (int u = 0; u < 8; ++u)
            a[u] = __ldcs((const float4*)(arow + seg + u * 128 + lane * 4));

#pragma unroll
        for (int u = 0; u < 8; ++u) {
            int jb = seg + u * 128 + lane * 4;
            unsigned m0 = __ballot_sync(0xffffffffu, a[u].x != 0.f);
            unsigned m1 = __ballot_sync(0xffffffffu, a[u].y != 0.f);
            unsigned m2 = __ballot_sync(0xffffffffu, a[u].z != 0.f);
            unsigned m3 = __ballot_sync(0xffffffffu, a[u].w != 0.f);
            int c0 = __popc(m0), c1 = __popc(m1), c2 = __popc(m2), c3 = __popc(m3);
            int tot = c0 + c1 + c2 + c3;
            int base = 0;
            if (tot) {
                if (lane == 0) base = atomicAdd(&s_cnt, tot);
                base = __shfl_sync(0xffffffffu, base, 0);
                if (a[u].x != 0.f) lst[base + __popc(m0 & lt)]                = (unsigned short)(jb);
                if (a[u].y != 0.f) lst[base + c0 + __popc(m1 & lt)]           = (unsigned short)(jb + 1);
                if (a[u].z != 0.f) lst[base + c0 + c1 + __popc(m2 & lt)]      = (unsigned short)(jb + 2);
                if (a[u].w != 0.f) lst[base + c0 + c1 + c2 + __popc(m3 & lt)] = (unsigned short)(jb + 3);
            }
        }
    }
    __syncthreads();
    if (tid == 0) g_cnt[row] = s_cnt;
    if (tid < 8) lst[s_cnt + tid] = 0;   // pad for ushort4 reads
}

// Prefetch one batch of 4 neighbor rows into (statically named) registers.
#define PREFETCH(VV, YY, PJ)                                                     \
    do {                                                                         \
        int _j0 = (PJ).x, _j1 = (PJ).y, _j2 = (PJ).z, _j3 = (PJ).w;              \
        (VV)[0] = *(const uint4*)(g_yn16 + (size_t)_j0 * (DDIM / 2) + lane * 4); \
        (VV)[1] = *(const uint4*)(g_yn16 + (size_t)_j1 * (DDIM / 2) + lane * 4); \
        (VV)[2] = *(const uint4*)(g_yn16 + (size_t)_j2 * (DDIM / 2) + lane * 4); \
        (VV)[3] = *(const uint4*)(g_yn16 + (size_t)_j3 * (DDIM / 2) + lane * 4); \
        (YY)[0] = __ldg(&g_ynorm[_j0]);                                          \
        (YY)[1] = __ldg(&g_ynorm[_j1]);                                          \
        (YY)[2] = __ldg(&g_ynorm[_j2]);                                          \
        (YY)[3] = __ldg(&g_ynorm[_j3]);                                          \
    } while (0)

// Process one batch of 4: half2 dots, packed 6-SHFL half2 reduction,
// fixed-shift softmax, fp16 P@y accumulation.
#define PROCESS(VV, YY, BASE)                                                    \
    do {                                                                         \
        __half2 dh0, dh1, dh2, dh3;                                              \
        {                                                                        \
            __half2 a;                                                           \
            a = __hmul2(xh0, *(const __half2*)&(VV)[0].x);                       \
            a = __hfma2(xh1, *(const __half2*)&(VV)[0].y, a);                    \
            a = __hfma2(xh2, *(const __half2*)&(VV)[0].z, a);                    \
            dh0 = __hfma2(xh3, *(const __half2*)&(VV)[0].w, a);                  \
            a = __hmul2(xh0, *(const __half2*)&(VV)[1].x);                       \
            a = __hfma2(xh1, *(const __half2*)&(VV)[1].y, a);                    \
            a = __hfma2(xh2, *(const __half2*)&(VV)[1].z, a);                    \
            dh1 = __hfma2(xh3, *(const __half2*)&(VV)[1].w, a);                  \
            a = __hmul2(xh0, *(const __half2*)&(VV)[2].x);                       \
            a = __hfma2(xh1, *(const __half2*)&(VV)[2].y, a);                    \
            a = __hfma2(xh2, *(const __half2*)&(VV)[2].z, a);                    \
            dh2 = __hfma2(xh3, *(const __half2*)&(VV)[2].w, a);                  \
            a = __hmul2(xh0, *(const __half2*)&(VV)[3].x);                       \
            a = __hfma2(xh1, *(const __half2*)&(VV)[3].y, a);                    \
            a = __hfma2(xh2, *(const __half2*)&(VV)[3].z, a);                    \
            dh3 = __hfma2(xh3, *(const __half2*)&(VV)[3].w, a);                  \
        }                                                                        \
        {                                                                        \
            __half2 s0 = lo16 ? dh2 : dh0;                                       \
            dh0 = __hadd2(lo16 ? dh0 : dh2, h2shfl_xor(s0, 16));                 \
            __half2 s1 = lo16 ? dh3 : dh1;                                       \
            dh1 = __hadd2(lo16 ? dh1 : dh3, h2shfl_xor(s1, 16));                 \
            __half2 s2 = lo8 ? dh1 : dh0;                                        \
            dh0 = __hadd2(lo8 ? dh0 : dh1, h2shfl_xor(s2, 8));                   \
            dh0 = __hadd2(dh0, h2shfl_xor(dh0, 4));                              \
            dh0 = __hadd2(dh0, h2shfl_xor(dh0, 2));                              \
            dh0 = __hadd2(dh0, h2shfl_xor(dh0, 1));                              \
        }                                                                        \
        float2 cf = __half22float2(dh0);                                         \
        float e = __expf(cf.x + cf.y - 1.0f);                                    \
        float e0 = __shfl_sync(0xffffffffu, e, 0);                               \
        float e1 = __shfl_sync(0xffffffffu, e, 8);                               \
        float e2 = __shfl_sync(0xffffffffu, e, 16);                              \
        float e3 = __shfl_sync(0xffffffffu, e, 24);                              \
        float p0 = ((BASE) + 0 < cnt) ? e0 : 0.f;                                \
        float p1 = ((BASE) + 1 < cnt) ? e1 : 0.f;                                \
        float p2 = ((BASE) + 2 < cnt) ? e2 : 0.f;                                \
        float p3 = ((BASE) + 3 < cnt) ? e3 : 0.f;                                \
        l += p0 + p1 + p2 + p3;                                                  \
        __half2 ph;                                                             \
        ph = __float2half2_rn(p0 * (YY)[0]);                                     \
        oh0 = __hfma2(ph, *(const __half2*)&(VV)[0].x, oh0);                     \
        oh1 = __hfma2(ph, *(const __half2*)&(VV)[0].y, oh1);                     \
        oh2 = __hfma2(ph, *(const __half2*)&(VV)[0].z, oh2);                     \
        oh3 = __hfma2(ph, *(const __half2*)&(VV)[0].w, oh3);                     \
        ph = __float2half2_rn(p1 * (YY)[1]);                                     \
        oh0 = __hfma2(ph, *(const __half2*)&(VV)[1].x, oh0);                     \
        oh1 = __hfma2(ph, *(const __half2*)&(VV)[1].y, oh1);                     \
        oh2 = __hfma2(ph, *(const __half2*)&(VV)[1].z, oh2);                     \
        oh3 = __hfma2(ph, *(const __half2*)&(VV)[1].w, oh3);                     \
        ph = __float2half2_rn(p2 * (YY)[2]);                                     \
        oh0 = __hfma2(ph, *(const __half2*)&(VV)[2].x, oh0);                     \
        oh1 = __hfma2(ph, *(const __half2*)&(VV)[2].y, oh1);                     \
        oh2 = __hfma2(ph, *(const __half2*)&(VV)[2].z, oh2);                     \
        oh3 = __hfma2(ph, *(const __half2*)&(VV)[2].w, oh3);                     \
        ph = __float2half2_rn(p3 * (YY)[3]);                                     \
        oh0 = __hfma2(ph, *(const __half2*)&(VV)[3].x, oh0);                     \
        oh1 = __hfma2(ph, *(const __half2*)&(VV)[3].y, oh1);                     \
        oh2 = __hfma2(ph, *(const __half2*)&(VV)[3].z, oh2);                     \
        oh3 = __hfma2(ph, *(const __half2*)&(VV)[3].w, oh3);                     \
    } while (0)

#define FLUSH()                                                                  \
    do {                                                                         \
        float2 f0 = __half22float2(oh0), f1 = __half22float2(oh1);               \
        float2 f2 = __half22float2(oh2), f3 = __half22float2(oh3);               \
        o0 += f0.x; o1 += f0.y; o2 += f1.x; o3 += f1.y;                          \
        o4 += f2.x; o5 += f2.y; o6 += f3.x; o7 += f3.y;                          \
        __half2 z = __float2half2_rn(0.f);                                       \
        oh0 = z; oh1 = z; oh2 = z; oh3 = z;                                      \
    } while (0)

// One WARP per output row, software-pipelined with STATIC double buffers
// (loop unrolled x2 so all buffer indices are compile-time).
__global__ void __launch_bounds__(256) gat_main(const float* __restrict__ x,
                                                float* __restrict__ out,
                                                int N, int M) {
    const int warp = (blockIdx.x * blockDim.x + threadIdx.x) >> 5;
    const int lane = threadIdx.x & 31;
    if (warp >= N) return;
    const int i = warp;

    // ---- Load + normalize x row (lane owns dims [8l, 8l+8)) ----
    const float4* xp = (const float4*)(x + (size_t)i * DDIM);
    float4 xa = xp[lane * 2];
    float4 xb = xp[lane * 2 + 1];
    float ss = xa.x * xa.x + xa.y * xa.y + xa.z * xa.z + xa.w * xa.w
             + xb.x * xb.x + xb.y * xb.y + xb.z * xb.z + xb.w * xb.w;
    ss = warp_sum(ss);
    float xinv = 1.0f / fmaxf(sqrtf(ss), 1e-8f);

    __half2 xh0 = __floats2half2_rn(xa.x * xinv, xa.y * xinv);
    __half2 xh1 = __floats2half2_rn(xa.z * xinv, xa.w * xinv);
    __half2 xh2 = __floats2half2_rn(xb.x * xinv, xb.y * xinv);
    __half2 xh3 = __floats2half2_rn(xb.z * xinv, xb.w * xinv);

    const int cnt = g_cnt[i];
    const unsigned short* glst = g_list + (size_t)i * LISTCAP;
    const int nb = (cnt + BW - 1) / BW;

    float o0 = 0.f, o1 = 0.f, o2 = 0.f, o3 = 0.f;
    float o4 = 0.f, o5 = 0.f, o6 = 0.f, o7 = 0.f;
    __half2 oh0 = __float2half2_rn(0.f);
    __half2 oh1 = oh0, oh2 = oh0, oh3 = oh0;
    float l = 0.f;

    const bool lo16 = (lane & 16) == 0;
    const bool lo8  = (lane & 8)  == 0;

    // ---- Static double buffers ----
    ushort4 pj0, pj1;
    uint4   v0[BW], v1[BW];
    float   yn0[BW], yn1[BW];

    pj0 = *(const ushort4*)(glst);
    if (nb > 1) pj1 = *(const ushort4*)(glst + 4);
    PREFETCH(v0, yn0, pj0);

    for (int b = 0; b < nb; b += 2) {
        // even iteration: consume buffer 0, prefetch buffer 1
        if (b + 1 < nb) PREFETCH(v1, yn1, pj1);
        if (b + 2 < nb) pj0 = *(const ushort4*)(glst + (b + 2) * 4);
        PROCESS(v0, yn0, b * BW);

        // odd iteration: consume buffer 1, prefetch buffer 0
        if (b + 1 < nb) {
            if (b + 2 < nb) PREFETCH(v0, yn0, pj0);
            if (b + 3 < nb) pj1 = *(const ushort4*)(glst + (b + 3) * 4);
            PROCESS(v1, yn1, (b + 1) * BW);
        }

        // Flush half2 partials to fp32 every 8 batches (32 neighbors).
        if ((b & 7) == 6) FLUSH();
    }
    FLUSH();

    float s = 0.5f / l;   // l > 0 guaranteed (diagonal entry in adj)
    float4 r0, r1;
    r0.x = fmaf(s, o0, 0.5f * xa.x);
    r0.y = fmaf(s, o1, 0.5f * xa.y);
    r0.z = fmaf(s, o2, 0.5f * xa.z);
    r0.w = fmaf(s, o3, 0.5f * xa.w);
    r1.x = fmaf(s, o4, 0.5f * xb.x);
    r1.y = fmaf(s, o5, 0.5f * xb.y);
    r1.z = fmaf(s, o6, 0.5f * xb.z);
    r1.w = fmaf(s, o7, 0.5f * xb.w);

    float4* op = (float4*)(out + (size_t)i * DDIM);
    op[lane * 2]     = r0;
    op[lane * 2 + 1] = r1;
}

extern "C" void kernel_launch(void* const* d_in, const int* in_sizes, int n_in,
                              void* d_out, int out_size) {
    const float* x   = (const float*)d_in[0];
    const float* y   = (const float*)d_in[1];
    const float* adj = (const float*)d_in[2];
    float* out       = (float*)d_out;

    int N = in_sizes[0] / DDIM;   // 8192
    int M = in_sizes[1] / DDIM;   // 8192

    csr_scan<<<N, 256>>>(adj, y, M);

    int main_blocks = (N * 32 + 255) / 256;
    gat_main<<<main_blocks, 256>>>(x, out, N, M);
}

// round 12
// speedup vs baseline: 2.1718x; 1.0854x over previous
#include <cuda_runtime.h>
#include <cuda_fp16.h>

#define DDIM    256
#define NMAX    8192
#define LISTCAP 768     // mean nnz ~164, sd ~12.7; cnt+8 pad always fits
#define BW      4       // batch (software-pipelined)

// Scratch: NORMALIZED y rows in fp16 (4 MB, L2-resident) + norms (fp32)
// + CSR-style neighbor lists built by csr_scan.
__device__ __half2        g_yn16[(size_t)NMAX * (DDIM / 2)];
__device__ float          g_ynorm[NMAX];
__device__ unsigned short g_list[(size_t)NMAX * LISTCAP];
__device__ int            g_cnt[NMAX];

__device__ __forceinline__ float warp_sum(float v) {
#pragma unroll
    for (int off = 16; off; off >>= 1)
        v += __shfl_xor_sync(0xffffffffu, v, off);
    return v;
}

// Single-instruction integer warp reduction (sm_80+; fp32 redux doesn't
// exist on sm_100, so we go through fixed point).
__device__ __forceinline__ int redux_add_s32(int v) {
    int r;
    asm("redux.sync.add.s32 %0, %1, 0xffffffff;" : "=r"(r) : "r"(v));
    return r;
}

// Streaming pass: one CTA per adj row. 8 warps scan disjoint 1024-col
// segments (8 float4 loads in flight), ballot-compact nonzero indices.
// Warp 0 additionally preps y row `row`. Tail zero-padded for ushort4 reads.
__global__ void __launch_bounds__(256) csr_scan(const float* __restrict__ adj,
                                                const float* __restrict__ y,
                                                int M) {
    __shared__ int s_cnt;
    const int row  = blockIdx.x;
    const int tid  = threadIdx.x;
    const int wib  = tid >> 5;
    const int lane = tid & 31;

    if (tid == 0) s_cnt = 0;
    __syncthreads();

    // ---- warp 0: prep y row (independent of scan) ----
    if (wib == 0 && row < M) {
        const float4* yp = (const float4*)(y + (size_t)row * DDIM);
        float4 a = yp[lane * 2];
        float4 b = yp[lane * 2 + 1];
        float ss = a.x * a.x + a.y * a.y + a.z * a.z + a.w * a.w
                 + b.x * b.x + b.y * b.y + b.z * b.z + b.w * b.w;
        ss = warp_sum(ss);
        float n   = fmaxf(sqrtf(ss), 1e-8f);
        float inv = 1.0f / n;
        if (lane == 0) g_ynorm[row] = n;
        __half2* o = g_yn16 + (size_t)row * (DDIM / 2) + lane * 4;
        o[0] = __floats2half2_rn(a.x * inv, a.y * inv);
        o[1] = __floats2half2_rn(a.z * inv, a.w * inv);
        o[2] = __floats2half2_rn(b.x * inv, b.y * inv);
        o[3] = __floats2half2_rn(b.z * inv, b.w * inv);
    }

    const float* arow = adj + (size_t)row * M;
    unsigned short* lst = g_list + (size_t)row * LISTCAP;
    const unsigned lt = (1u << lane) - 1u;

    for (int seg = wib * 1024; seg < M; seg += 8 * 1024) {
        float4 a[8];
#pragma unroll
        for (int u = 0; u < 8; ++u)
            a[u] = __ldcs((const float4*)(arow + seg + u * 128 + lane * 4));

#pragma unroll
        for (int u = 0; u < 8; ++u) {
            int jb = seg + u * 128 + lane * 4;
            unsigned m0 = __ballot_sync(0xffffffffu, a[u].x != 0.f);
            unsigned m1 = __ballot_sync(0xffffffffu, a[u].y != 0.f);
            unsigned m2 = __ballot_sync(0xffffffffu, a[u].z != 0.f);
            unsigned m3 = __ballot_sync(0xffffffffu, a[u].w != 0.f);
            int c0 = __popc(m0), c1 = __popc(m1), c2 = __popc(m2), c3 = __popc(m3);
            int tot = c0 + c1 + c2 + c3;
            int base = 0;
            if (tot) {
                if (lane == 0) base = atomicAdd(&s_cnt, tot);
                base = __shfl_sync(0xffffffffu, base, 0);
                if (a[u].x != 0.f) lst[base + __popc(m0 & lt)]                = (unsigned short)(jb);
                if (a[u].y != 0.f) lst[base + c0 + __popc(m1 & lt)]           = (unsigned short)(jb + 1);
                if (a[u].z != 0.f) lst[base + c0 + c1 + __popc(m2 & lt)]      = (unsigned short)(jb + 2);
                if (a[u].w != 0.f) lst[base + c0 + c1 + c2 + __popc(m3 & lt)] = (unsigned short)(jb + 3);
            }
        }
    }
    __syncthreads();
    if (tid == 0) g_cnt[row] = s_cnt;
    if (tid < 8) lst[s_cnt + tid] = 0;   // pad for ushort4 reads
}

// Prefetch one batch of 4 neighbor rows into (statically named) registers.
#define PREFETCH(VV, YY, PJ)                                                     \
    do {                                                                         \
        int _j0 = (PJ).x, _j1 = (PJ).y, _j2 = (PJ).z, _j3 = (PJ).w;              \
        (VV)[0] = *(const uint4*)(g_yn16 + (size_t)_j0 * (DDIM / 2) + lane * 4); \
        (VV)[1] = *(const uint4*)(g_yn16 + (size_t)_j1 * (DDIM / 2) + lane * 4); \
        (VV)[2] = *(const uint4*)(g_yn16 + (size_t)_j2 * (DDIM / 2) + lane * 4); \
        (VV)[3] = *(const uint4*)(g_yn16 + (size_t)_j3 * (DDIM / 2) + lane * 4); \
        (YY)[0] = __ldg(&g_ynorm[_j0]);                                          \
        (YY)[1] = __ldg(&g_ynorm[_j1]);                                          \
        (YY)[2] = __ldg(&g_ynorm[_j2]);                                          \
        (YY)[3] = __ldg(&g_ynorm[_j3]);                                          \
    } while (0)

// Process one batch of 4: half2 dots, fixed-point REDUX warp reduction
// (one instruction, result in every lane -> no broadcast), fixed-shift
// softmax, fp16 P@y accumulation. All 4 neighbors independent -> ILP.
#define PROCESS(VV, YY, BASE)                                                    \
    do {                                                                         \
        _Pragma("unroll")                                                        \
        for (int k = 0; k < BW; ++k) {                                           \
            __half2 a = __hmul2(xh0, *(const __half2*)&(VV)[k].x);               \
            a = __hfma2(xh1, *(const __half2*)&(VV)[k].y, a);                    \
            a = __hfma2(xh2, *(const __half2*)&(VV)[k].z, a);                    \
            a = __hfma2(xh3, *(const __half2*)&(VV)[k].w, a);                    \
            float2 cf = __half22float2(a);                                       \
            int qi = __float2int_rn((cf.x + cf.y) * 4194304.0f);                 \
            qi = redux_add_s32(qi);                                              \
            float e = __expf(fmaf((float)qi, 2.384185791015625e-7f, -1.0f));     \
            float p = ((BASE) + k < cnt) ? e : 0.f;                              \
            l += p;                                                              \
            __half2 ph = __float2half2_rn(p * (YY)[k]);                          \
            oh0 = __hfma2(ph, *(const __half2*)&(VV)[k].x, oh0);                 \
            oh1 = __hfma2(ph, *(const __half2*)&(VV)[k].y, oh1);                 \
            oh2 = __hfma2(ph, *(const __half2*)&(VV)[k].z, oh2);                 \
            oh3 = __hfma2(ph, *(const __half2*)&(VV)[k].w, oh3);                 \
        }                                                                        \
    } while (0)

#define FLUSH()                                                                  \
    do {                                                                         \
        float2 f0 = __half22float2(oh0), f1 = __half22float2(oh1);               \
        float2 f2 = __half22float2(oh2), f3 = __half22float2(oh3);               \
        o0 += f0.x; o1 += f0.y; o2 += f1.x; o3 += f1.y;                          \
        o4 += f2.x; o5 += f2.y; o6 += f3.x; o7 += f3.y;                          \
        __half2 z = __float2half2_rn(0.f);                                       \
        oh0 = z; oh1 = z; oh2 = z; oh3 = z;                                      \
    } while (0)

// One WARP per output row, software-pipelined with STATIC double buffers
// (loop unrolled x2 so all buffer indices are compile-time). Block=128 for
// finer occupancy granularity at ~85 regs.
__global__ void __launch_bounds__(128) gat_main(const float* __restrict__ x,
                                                float* __restrict__ out,
                                                int N, int M) {
    const int warp = (blockIdx.x * blockDim.x + threadIdx.x) >> 5;
    const int lane = threadIdx.x & 31;
    if (warp >= N) return;
    const int i = warp;

    // ---- Load + normalize x row (lane owns dims [8l, 8l+8)) ----
    const float4* xp = (const float4*)(x + (size_t)i * DDIM);
    float4 xa = xp[lane * 2];
    float4 xb = xp[lane * 2 + 1];
    float ss = xa.x * xa.x + xa.y * xa.y + xa.z * xa.z + xa.w * xa.w
             + xb.x * xb.x + xb.y * xb.y + xb.z * xb.z + xb.w * xb.w;
    ss = warp_sum(ss);
    float xinv = 1.0f / fmaxf(sqrtf(ss), 1e-8f);

    __half2 xh0 = __floats2half2_rn(xa.x * xinv, xa.y * xinv);
    __half2 xh1 = __floats2half2_rn(xa.z * xinv, xa.w * xinv);
    __half2 xh2 = __floats2half2_rn(xb.x * xinv, xb.y * xinv);
    __half2 xh3 = __floats2half2_rn(xb.z * xinv, xb.w * xinv);

    const int cnt = g_cnt[i];
    const unsigned short* glst = g_list + (size_t)i * LISTCAP;
    const int nb = (cnt + BW - 1) / BW;

    float o0 = 0.f, o1 = 0.f, o2 = 0.f, o3 = 0.f;
    float o4 = 0.f, o5 = 0.f, o6 = 0.f, o7 = 0.f;
    __half2 oh0 = __float2half2_rn(0.f);
    __half2 oh1 = oh0, oh2 = oh0, oh3 = oh0;
    float l = 0.f;

    // ---- Static double buffers ----
    ushort4 pj0, pj1;
    uint4   v0[BW], v1[BW];
    float   yn0[BW], yn1[BW];

    pj0 = *(const ushort4*)(glst);
    if (nb > 1) pj1 = *(const ushort4*)(glst + 4);
    PREFETCH(v0, yn0, pj0);

    for (int b = 0; b < nb; b += 2) {
        // even iteration: consume buffer 0, prefetch buffer 1
        if (b + 1 < nb) PREFETCH(v1, yn1, pj1);
        if (b + 2 < nb) pj0 = *(const ushort4*)(glst + (b + 2) * 4);
        PROCESS(v0, yn0, b * BW);

        // odd iteration: consume buffer 1, prefetch buffer 0
        if (b + 1 < nb) {
            if (b + 2 < nb) PREFETCH(v0, yn0, pj0);
            if (b + 3 < nb) pj1 = *(const ushort4*)(glst + (b + 3) * 4);
            PROCESS(v1, yn1, (b + 1) * BW);
        }

        // Flush half2 partials to fp32 every 8 batches (32 neighbors).
        if ((b & 7) == 6) FLUSH();
    }
    FLUSH();

    float s = 0.5f / l;   // l > 0 guaranteed (diagonal entry in adj)
    float4 r0, r1;
    r0.x = fmaf(s, o0, 0.5f * xa.x);
    r0.y = fmaf(s, o1, 0.5f * xa.y);
    r0.z = fmaf(s, o2, 0.5f * xa.z);
    r0.w = fmaf(s, o3, 0.5f * xa.w);
    r1.x = fmaf(s, o4, 0.5f * xb.x);
    r1.y = fmaf(s, o5, 0.5f * xb.y);
    r1.z = fmaf(s, o6, 0.5f * xb.z);
    r1.w = fmaf(s, o7, 0.5f * xb.w);

    float4* op = (float4*)(out + (size_t)i * DDIM);
    op[lane * 2]     = r0;
    op[lane * 2 + 1] = r1;
}

extern "C" void kernel_launch(void* const* d_in, const int* in_sizes, int n_in,
                              void* d_out, int out_size) {
    const float* x   = (const float*)d_in[0];
    const float* y   = (const float*)d_in[1];
    const float* adj = (const float*)d_in[2];
    float* out       = (float*)d_out;

    int N = in_sizes[0] / DDIM;   // 8192
    int M = in_sizes[1] / DDIM;   // 8192

    csr_scan<<<N, 256>>>(adj, y, M);

    int main_blocks = (N * 32 + 127) / 128;
    gat_main<<<main_blocks, 128>>>(x, out, N, M);
}